// round 12
// baseline (speedup 1.0000x reference)
#include <cuda_runtime.h>

#define FULLMASK 0xffffffffu

__device__ __forceinline__ float redsum16(float v) {
    v += __shfl_xor_sync(FULLMASK, v, 8);
    v += __shfl_xor_sync(FULLMASK, v, 4);
    v += __shfl_xor_sync(FULLMASK, v, 2);
    v += __shfl_xor_sync(FULLMASK, v, 1);
    return v;
}
__device__ __forceinline__ float redmax16(float v) {
    v = fmaxf(v, __shfl_xor_sync(FULLMASK, v, 8));
    v = fmaxf(v, __shfl_xor_sync(FULLMASK, v, 4));
    v = fmaxf(v, __shfl_xor_sync(FULLMASK, v, 2));
    v = fmaxf(v, __shfl_xor_sync(FULLMASK, v, 1));
    return v;
}

// Fused: each warp handles 16 patches. Hot loop per patch does ONLY the cheap
// collectives (reduce 8 shfl + norm 5 + softmax 8 = 21 shfl vs ~60 before) and
// banks softmax weights to smem. Then a batched stats phase: 16 lanes each
// process one full patch scalar (top-5 / moments / threshold / mask / renorm,
// zero shfl). This slashes MIO-path (SHFL/MUFU) pressure interleaved with the
// load stream, which the evidence says is what caps DRAM at ~5.4 TB/s.
__global__ void __launch_bounds__(256) router_kernel(
    const float* __restrict__ patch,
    const float* __restrict__ keys,
    const float* __restrict__ p_temp,
    const float* __restrict__ p_beta,
    const float* __restrict__ p_thr,
    float* __restrict__ out,
    int n_patches)
{
    __shared__ float s_keys[16 * 33];     // stride-33 pad, conflict-free spread
    __shared__ float s_raw[8][32];        // per-warp channel sums (reused)
    __shared__ float s_w[8][16][17];      // [warp][patch-in-batch][expert], pad 17

    const int tid  = threadIdx.x;
    const int wid  = tid >> 5;
    const int lane = tid & 31;

    for (int i = tid; i < 16 * 32; i += 256)
        s_keys[(i >> 5) * 33 + (i & 31)] = keys[i];
    __syncthreads();

    const int n0 = blockIdx.x * 128 + wid * 16;   // warp's first patch
    if (n0 >= n_patches) return;                   // warp-uniform

    const float logit_temp = __ldg(p_temp);
    const float mask_beta  = __ldg(p_beta);
    const float thr_base   = __ldg(p_thr);

    const int e = lane & 15;
    const int lidx = (lane >> 2) * 16 + (lane & 3);   // grouped 64B-chunk index

    // =================== HOT LOOP: 16 patches ===================
#pragma unroll 1
    for (int i = 0; i < 16; i++) {
        const int n = n0 + i;
        if (n >= n_patches) break;                 // uniform across warp

        const float4* p4 = reinterpret_cast<const float4*>(patch) + (size_t)n * 512;

        // Two halves of 8 x LDG.128 (grouped pattern: 8 lines/LDG, 4KB in flight)
#pragma unroll
        for (int h = 0; h < 2; h++) {
            float4 v[8];
#pragma unroll
            for (int t = 0; t < 8; t++)
                v[t] = p4[(h * 2 + (t >> 2)) * 128 + lidx + 4 * (t & 3)];
#pragma unroll
            for (int pp = 0; pp < 2; pp++) {
                float a = 0.0f;
#pragma unroll
                for (int q = 0; q < 4; q++) {
                    const float4 x = v[pp * 4 + q];
                    a += (x.x + x.y) + (x.z + x.w);
                }
                a += __shfl_xor_sync(FULLMASK, a, 1);
                a += __shfl_xor_sync(FULLMASK, a, 2);
                if ((lane & 3) == 0)
                    s_raw[wid][(h * 2 + pp) * 8 + (lane >> 2)] = a;
            }
        }
        __syncwarp();

        // L2 norm over 32 channel sums (5 shfl)
        const float rc = s_raw[wid][lane];
        float sq = rc * rc;
        sq += __shfl_xor_sync(FULLMASK, sq, 16);
        sq += __shfl_xor_sync(FULLMASK, sq, 8);
        sq += __shfl_xor_sync(FULLMASK, sq, 4);
        sq += __shfl_xor_sync(FULLMASK, sq, 2);
        sq += __shfl_xor_sync(FULLMASK, sq, 1);
        const float denom = fmaxf(sqrtf(sq), 64.0f * 1e-12f);

        // Logits (lane=expert, halves mirror) — broadcast smem + spread keys
        float dot = 0.0f;
#pragma unroll
        for (int c = 0; c < 32; c++)
            dot = fmaf(s_raw[wid][c], s_keys[e * 33 + c], dot);

        const float sl = (dot / denom) / logit_temp + 1e-8f;

        // Softmax over 16 (8 shfl)
        const float m  = redmax16(sl);
        const float ex = __expf(sl - m);
        const float S  = redsum16(ex);
        const float w  = ex / S;

        if (lane < 16)
            s_w[wid][i][e] = w;
        __syncwarp();
    }

    // =================== STATS PHASE: 1 patch per lane, scalar ===================
    const int n = n0 + lane;                     // lanes 0..15 own patches
    if (lane < 16 && n < n_patches) {
        float w[16];
#pragma unroll
        for (int c = 0; c < 16; c++) w[c] = s_w[wid][lane][c];   // conflict-free (17 odd)

        // Top-5 via selection (values only; verified in R8)
        float t[16];
#pragma unroll
        for (int c = 0; c < 16; c++) t[c] = w[c];
        float top[5];
#pragma unroll
        for (int k = 0; k < 5; k++) {
            float best = t[0]; int bi = 0;
#pragma unroll
            for (int c = 1; c < 16; c++)
                if (t[c] > best) { best = t[c]; bi = c; }
            top[k] = best;
            t[bi] = -1.0f;
        }
        const float s0   = top[0];
        const float rest = (top[1] + top[2] + top[3] + top[4]) * 0.25f;
        const float kth  = top[3];

        // Moments & entropy
        float sum = 0.0f, ent = 0.0f;
#pragma unroll
        for (int c = 0; c < 16; c++) {
            sum += w[c];
            ent -= w[c] * __logf(w[c] + 1e-18f);
        }
        const float meanw = sum * (1.0f / 16.0f);
        float var = 0.0f;
#pragma unroll
        for (int c = 0; c < 16; c++) {
            const float d = w[c] - meanw;
            var = fmaf(d, d, var);
        }
        const float stdw = sqrtf(var * (1.0f / 15.0f));   // ddof=1

        // Adaptive threshold
        const float maxc = 1.0f - s0;
        const float entc = 1.0f - ent * (1.0f / 2.7725887222397811f);  // 1/log(16)
        float gap = (s0 - rest) / (s0 + 1e-8f);
        gap = fminf(fmaxf(gap, 0.0f), 1.0f);
        const float af = 0.4f * maxc + 0.3f * entc + 0.3f * gap;
        float adaptive = thr_base * (0.5f + af);
        const float min_thr = fmaxf(0.05f, meanw - 0.5f * stdw);
        const float max_thr = fminf(0.7f, s0 - 0.1f * stdw);
        adaptive = fminf(fmaxf(adaptive, min_thr), max_thr);
        adaptive = fminf(adaptive, kth * 0.9f);

        // Soft mask + renormalize
        float wf[16];
        float swf = 0.0f;
#pragma unroll
        for (int c = 0; c < 16; c++) {
            const float x  = (mask_beta + 1e-8f) * (w[c] - adaptive);
            const float sm = 1.0f / (1.0f + __expf(-x));
            wf[c] = w[c] * sm;
            swf += wf[c];
        }
        const float inv = 1.0f / fmaxf(swf, 1e-8f);

        float4* o4 = reinterpret_cast<float4*>(out + (size_t)n * 16);
#pragma unroll
        for (int j = 0; j < 4; j++) {
            float4 r;
            r.x = wf[j * 4 + 0] * inv; r.y = wf[j * 4 + 1] * inv;
            r.z = wf[j * 4 + 2] * inv; r.w = wf[j * 4 + 3] * inv;
            o4[j] = r;
        }
    }
}

extern "C" void kernel_launch(void* const* d_in, const int* in_sizes, int n_in,
                              void* d_out, int out_size) {
    const float* patch = (const float*)d_in[0];
    const float* keys  = (const float*)d_in[1];
    const float* temp  = (const float*)d_in[2];
    const float* beta  = (const float*)d_in[3];
    const float* thr   = (const float*)d_in[4];
    float* out = (float*)d_out;

    const int n_patches = in_sizes[0] / (32 * 8 * 8);
    const int blocks = (n_patches + 127) / 128;   // 8 warps x 16 patches
    router_kernel<<<blocks, 256>>>(patch, keys, temp, beta, thr, out, n_patches);
}